// round 1
// baseline (speedup 1.0000x reference)
#include <cuda_runtime.h>

// LinearAttentionCell with T=1 reduces algebraically to out = x @ Wv^T:
//   memory = outer(k, v); mem_read = (q.k) * v; scale = (q.k)  =>  out = v.
// So we compute only v = x @ Wv^T.  M=64, N=2048, K=2048, fp32 NT-GEMM.

#define MM 64
#define NN 2048
#define KK 2048
#define BN 32
#define BK 32
#define SPLITK 8
#define KCHUNK (KK / SPLITK)   // 256
#define THREADS 256

// split-K partials scratch: 8 * 64 * 2048 floats = 4 MB (L2-resident)
__device__ float g_part[SPLITK * MM * NN];

__device__ __forceinline__ unsigned long long pack2(float lo, float hi) {
    unsigned long long r;
    asm("mov.b64 %0, {%1, %2};" : "=l"(r) : "f"(lo), "f"(hi));
    return r;
}

__device__ __forceinline__ void fma2(unsigned long long& d,
                                     unsigned long long a,
                                     unsigned long long b) {
    // packed fp32x2 FMA (Blackwell): d = a*b + d, lanewise
    asm("fma.rn.f32x2 %0, %1, %2, %0;" : "+l"(d) : "l"(a), "l"(b));
}

__global__ __launch_bounds__(THREADS)
void gemm_v_kernel(const float* __restrict__ x, const float* __restrict__ Wv) {
    // k-major smem tiles, padded to dodge store conflicts; rows stay 16B-aligned
    __shared__ __align__(16) float xs[BK][MM + 4];   // 32 x 68
    __shared__ __align__(16) float ws[BK][BN + 4];   // 32 x 36

    const int tid = threadIdx.x;
    const int n0  = blockIdx.x * BN;
    const int k0  = blockIdx.y * KCHUNK;

    const int tm4 = (tid & 15) * 4;   // 16 groups cover m = 0..63
    const int tn2 = (tid >> 4) * 2;   // 16 groups cover n = 0..31

    unsigned long long acc[2][2];
    acc[0][0] = acc[0][1] = acc[1][0] = acc[1][1] = 0ull;

    for (int ko = 0; ko < KCHUNK; ko += BK) {
        const int kbase = k0 + ko;

        // load x tile [64 x 32] -> xs[k][m]  (512 float4, 2 per thread)
        #pragma unroll
        for (int r = 0; r < 2; r++) {
            int t  = tid + r * THREADS;
            int m  = t >> 3;
            int kf = (t & 7) * 4;
            float4 v = *reinterpret_cast<const float4*>(&x[m * KK + kbase + kf]);
            xs[kf + 0][m] = v.x;
            xs[kf + 1][m] = v.y;
            xs[kf + 2][m] = v.z;
            xs[kf + 3][m] = v.w;
        }
        // load Wv tile [32 x 32] -> ws[k][n]  (256 float4, 1 per thread)
        {
            int n  = tid >> 3;
            int kf = (tid & 7) * 4;
            float4 v = *reinterpret_cast<const float4*>(&Wv[(n0 + n) * KK + kbase + kf]);
            ws[kf + 0][n] = v.x;
            ws[kf + 1][n] = v.y;
            ws[kf + 2][n] = v.z;
            ws[kf + 3][n] = v.w;
        }
        __syncthreads();

        #pragma unroll
        for (int kk = 0; kk < BK; kk++) {
            // a: 4 contiguous m values, loaded directly as two packed f32x2
            ulonglong2 av = *reinterpret_cast<const ulonglong2*>(&xs[kk][tm4]);
            float2 b = *reinterpret_cast<const float2*>(&ws[kk][tn2]);
            unsigned long long b00 = pack2(b.x, b.x);
            unsigned long long b11 = pack2(b.y, b.y);
            fma2(acc[0][0], av.x, b00);
            fma2(acc[0][1], av.x, b11);
            fma2(acc[1][0], av.y, b00);
            fma2(acc[1][1], av.y, b11);
        }
        __syncthreads();
    }

    // epilogue: write split-K partials
    float* outp = &g_part[blockIdx.y * (MM * NN)];
    #pragma unroll
    for (int mi = 0; mi < 2; mi++) {
        #pragma unroll
        for (int ni = 0; ni < 2; ni++) {
            float lo, hi;
            asm("mov.b64 {%0, %1}, %2;" : "=f"(lo), "=f"(hi) : "l"(acc[mi][ni]));
            int m = tm4 + mi * 2;
            int n = n0 + tn2 + ni;
            outp[m * NN + n]       = lo;  // low lane = first m of the pair
            outp[(m + 1) * NN + n] = hi;
        }
    }
}

__global__ __launch_bounds__(THREADS)
void reduce_kernel(float* __restrict__ out) {
    int idx = blockIdx.x * blockDim.x + threadIdx.x;  // float4 index
    const float4* p = reinterpret_cast<const float4*>(g_part);
    float4 s = p[idx];
    #pragma unroll
    for (int kb = 1; kb < SPLITK; kb++) {
        float4 v = p[kb * (MM * NN / 4) + idx];
        s.x += v.x; s.y += v.y; s.z += v.z; s.w += v.w;
    }
    reinterpret_cast<float4*>(out)[idx] = s;
}

extern "C" void kernel_launch(void* const* d_in, const int* in_sizes, int n_in,
                              void* d_out, int out_size) {
    // inputs: 0=x [64,1,2048] f32, 1=Wq, 2=bq, 3=Wk, 4=bk, 5=Wv [2048,2048] f32, 6=pos
    const float* x  = (const float*)d_in[0];
    const float* Wv = (const float*)d_in[5];
    float* out = (float*)d_out;

    dim3 grid(NN / BN, SPLITK);            // 64 x 8 = 512 blocks
    gemm_v_kernel<<<grid, THREADS>>>(x, Wv);

    int total4 = MM * NN / 4;              // 32768 float4
    reduce_kernel<<<total4 / THREADS, THREADS>>>(out);

    (void)in_sizes; (void)n_in; (void)out_size;
}

// round 3
// speedup vs baseline: 2.2689x; 2.2689x over previous
#include <cuda_runtime.h>
#include <cuda_bf16.h>
#include <cstdint>

// LinearAttentionCell with T=1 reduces algebraically to out = x @ Wv^T
// (memory = outer(k,v); mem_read = (q.k)*v; scale = (q.k) => out = v).
// Implemented as bf16 HMMA (mma.sync m16n8k16, baseline PTX — tcgen05 is
// rejected by this toolchain's compute_103 target) with 3-product Dekker
// splitting: fp32 = hi + lo (bf16);  D += Ahi*Bhi + Ahi*Blo + Alo*Bhi.
// M=64 (batch) x N=2048 (out channels) x K=2048.

#define KDIM 2048
#define NDIM 2048
#define MDIM 64
#define NT   128          // n per CTA
#define SPLITK 8
#define KCH  256          // k per CTA
#define KSTEPS_CTA 16     // KCH/16
#define GT   512          // gemm threads (16 warps: 4 m-rows x 4 n-cols)

// x pre-split into mma A-fragment order:
// [mb(4)][ks_global(128)][lane(32)] -> uint4 (a0..a3)
__device__ __align__(16) uint4 g_ahi[4 * 128 * 32];
__device__ __align__(16) uint4 g_alo[4 * 128 * 32];

// padded smem W tile: 128 rows x 32 k-pair words, row stride 36 words
#define PADW 36

__device__ __forceinline__ uint32_t cvt2(float hi_e, float lo_e) {
    // packs: low 16 = bf16(lo_e), high 16 = bf16(hi_e)
    uint32_t r;
    asm("cvt.rn.bf16x2.f32 %0, %1, %2;" : "=r"(r) : "f"(hi_e), "f"(lo_e));
    return r;
}

__device__ __forceinline__ void split4(float4 v, uint32_t& h01, uint32_t& h23,
                                       uint32_t& l01, uint32_t& l23) {
    h01 = cvt2(v.y, v.x);
    h23 = cvt2(v.w, v.z);
    float f0 = __uint_as_float(h01 << 16);
    float f1 = __uint_as_float(h01 & 0xFFFF0000u);
    float f2 = __uint_as_float(h23 << 16);
    float f3 = __uint_as_float(h23 & 0xFFFF0000u);
    l01 = cvt2(v.y - f1, v.x - f0);
    l23 = cvt2(v.w - f3, v.z - f2);
}

__device__ __forceinline__ void mma16816(float* d, const uint32_t* a,
                                         uint32_t b0, uint32_t b1) {
    asm volatile(
        "mma.sync.aligned.m16n8k16.row.col.f32.bf16.bf16.f32 "
        "{%0,%1,%2,%3}, {%4,%5,%6,%7}, {%8,%9}, {%0,%1,%2,%3};"
        : "+f"(d[0]), "+f"(d[1]), "+f"(d[2]), "+f"(d[3])
        : "r"(a[0]), "r"(a[1]), "r"(a[2]), "r"(a[3]), "r"(b0), "r"(b1));
}

// ---------------- kernel 1: x -> A-fragment hi/lo arrays ----------------
__global__ __launch_bounds__(256)
void convert_x_kernel(const float* __restrict__ x) {
    int t = blockIdx.x * 256 + threadIdx.x;   // 0..16383
    int mb   = t >> 12;
    int ks   = (t >> 5) & 127;
    int lane = t & 31;
    int g  = lane >> 2;
    int tt = lane & 3;
    int m0 = mb * 16 + g;
    int k0 = ks * 16 + 2 * tt;

    float2 p00 = *reinterpret_cast<const float2*>(&x[m0 * KDIM + k0]);
    float2 p10 = *reinterpret_cast<const float2*>(&x[(m0 + 8) * KDIM + k0]);
    float2 p01 = *reinterpret_cast<const float2*>(&x[m0 * KDIM + k0 + 8]);
    float2 p11 = *reinterpret_cast<const float2*>(&x[(m0 + 8) * KDIM + k0 + 8]);

    uint4 hi, lo;
    float4 v0 = make_float4(p00.x, p00.y, p10.x, p10.y);
    float4 v1 = make_float4(p01.x, p01.y, p11.x, p11.y);
    uint32_t h01, h23, l01, l23;
    split4(v0, h01, h23, l01, l23);
    hi.x = h01; hi.y = h23; lo.x = l01; lo.y = l23;
    split4(v1, h01, h23, l01, l23);
    hi.z = h01; hi.w = h23; lo.z = l01; lo.w = l23;

    g_ahi[t] = hi;
    g_alo[t] = lo;
}

// ---------------- kernel 2: bf16 HMMA GEMM, atomic split-K ----------------
__global__ __launch_bounds__(GT, 1)
void gemm_kernel(const float* __restrict__ Wv, float* __restrict__ out) {
    __shared__ uint32_t SH[128 * PADW];   // W hi, [row][k-pair word], pad 36
    __shared__ uint32_t SL[128 * PADW];   // W lo

    const int tid  = threadIdx.x;
    const int lane = tid & 31;
    const int wid  = tid >> 5;
    const int wrow = wid >> 2;     // m-block 0..3 (m16 each)
    const int wcol = wid & 3;      // n-group 0..3 (n32 each)
    const int g  = lane >> 2;
    const int tt = lane & 3;

    const int n0 = blockIdx.x * NT;
    const int k0 = blockIdx.y * KCH;

    // W loader mapping: warp covers 2 rows x 16 kf4 -> coalesced LDG.128
    const int lrow = tid >> 4;          // 0..31 (+32i)
    const int lkf  = (tid & 15) * 4;    // 0..60

    float acc[4][4];
#pragma unroll
    for (int i = 0; i < 4; i++)
#pragma unroll
        for (int j = 0; j < 4; j++) acc[i][j] = 0.f;

    float4 wr[4];
#pragma unroll
    for (int i = 0; i < 4; i++)
        wr[i] = *reinterpret_cast<const float4*>(
            &Wv[(n0 + lrow + i * 32) * KDIM + k0 + lkf]);

    for (int sc = 0; sc < 4; sc++) {
        __syncthreads();   // prior consumers done
        // convert + store W sub-chunk (rows x k64)
#pragma unroll
        for (int i = 0; i < 4; i++) {
            uint32_t h01, h23, l01, l23;
            split4(wr[i], h01, h23, l01, l23);
            int w = (lrow + i * 32) * PADW + (lkf >> 1);
            *reinterpret_cast<uint2*>(&SH[w]) = make_uint2(h01, h23);
            *reinterpret_cast<uint2*>(&SL[w]) = make_uint2(l01, l23);
        }
        if (sc < 3) {
#pragma unroll
            for (int i = 0; i < 4; i++)
                wr[i] = *reinterpret_cast<const float4*>(
                    &Wv[(n0 + lrow + i * 32) * KDIM + k0 + (sc + 1) * 64 + lkf]);
        }
        __syncthreads();   // tiles ready

#pragma unroll
        for (int ks = 0; ks < 4; ks++) {
            int ksg = blockIdx.y * KSTEPS_CTA + sc * 4 + ks;
            uint4 ah4 = g_ahi[(wrow * 128 + ksg) * 32 + lane];
            uint4 al4 = g_alo[(wrow * 128 + ksg) * 32 + lane];
            uint32_t ah[4] = {ah4.x, ah4.y, ah4.z, ah4.w};
            uint32_t al[4] = {al4.x, al4.y, al4.z, al4.w};
#pragma unroll
            for (int nf = 0; nf < 4; nf++) {
                int nrow = wcol * 32 + nf * 8 + g;
                int bw = nrow * PADW + ks * 8 + tt;   // bank = (4g+tt)%32: clean
                uint32_t bh0 = SH[bw], bh1 = SH[bw + 4];
                uint32_t bl0 = SL[bw], bl1 = SL[bw + 4];
                mma16816(acc[nf], ah, bh0, bh1);
                mma16816(acc[nf], ah, bl0, bl1);
                mma16816(acc[nf], al, bh0, bh1);
            }
        }
    }

    // epilogue: split-K combine via vector atomics into out
#pragma unroll
    for (int nf = 0; nf < 4; nf++) {
        int m = wrow * 16 + g;
        int n = n0 + wcol * 32 + nf * 8 + 2 * tt;
        atomicAdd(reinterpret_cast<float2*>(&out[m * NDIM + n]),
                  make_float2(acc[nf][0], acc[nf][1]));
        atomicAdd(reinterpret_cast<float2*>(&out[(m + 8) * NDIM + n]),
                  make_float2(acc[nf][2], acc[nf][3]));
    }
}

extern "C" void kernel_launch(void* const* d_in, const int* in_sizes, int n_in,
                              void* d_out, int out_size) {
    // inputs: 0=x [64,1,2048] f32, 1=Wq, 2=bq, 3=Wk, 4=bk, 5=Wv [2048,2048], 6=pos
    const float* x  = (const float*)d_in[0];
    const float* Wv = (const float*)d_in[5];
    float* out = (float*)d_out;

    cudaMemsetAsync(out, 0, (size_t)MDIM * NDIM * sizeof(float));
    convert_x_kernel<<<64, 256>>>(x);
    dim3 grid(NDIM / NT, SPLITK);   // 16 x 8 = 128 CTAs, one wave
    gemm_kernel<<<grid, GT>>>(Wv, out);

    (void)in_sizes; (void)n_in; (void)out_size;
}

// round 4
// speedup vs baseline: 2.6157x; 1.1529x over previous
#include <cuda_runtime.h>
#include <cuda_bf16.h>
#include <cstdint>

// LinearAttentionCell with T=1 reduces algebraically to out = x @ Wv^T
// (memory = outer(k,v); mem_read = (q.k)*v; scale = (q.k) => out = v).
// bf16 HMMA (mma.sync m16n8k16) with 3-product Dekker splitting:
//   fp32 = hi + lo (bf16);  D += Ahi*Bhi + Ahi*Blo + Alo*Bhi  (fp32 accum)
// M=64 (batch) x N=2048 (out channels) x K=2048.
// R4: A-fragment register double-buffer (hide L2 latency), B LDS hoisted,
// MMAs product-major so 4 independent accumulators break RAW chains.

#define KDIM 2048
#define NDIM 2048
#define MDIM 64
#define NT   128          // n per CTA
#define SPLITK 8
#define KCH  256          // k per CTA
#define KSTEPS_CTA 16     // KCH/16
#define GT   512          // gemm threads (16 warps: 4 m-rows x 4 n-cols)

// x pre-split into mma A-fragment order:
// [mb(4)][ks_global(128)][lane(32)] -> uint4 (a0..a3)
__device__ __align__(16) uint4 g_ahi[4 * 128 * 32];
__device__ __align__(16) uint4 g_alo[4 * 128 * 32];

// padded smem W tile: 128 rows x 32 k-pair words, row stride 36 words
#define PADW 36

__device__ __forceinline__ uint32_t cvt2(float hi_e, float lo_e) {
    // packs: low 16 = bf16(lo_e), high 16 = bf16(hi_e)
    uint32_t r;
    asm("cvt.rn.bf16x2.f32 %0, %1, %2;" : "=r"(r) : "f"(hi_e), "f"(lo_e));
    return r;
}

__device__ __forceinline__ void split4(float4 v, uint32_t& h01, uint32_t& h23,
                                       uint32_t& l01, uint32_t& l23) {
    h01 = cvt2(v.y, v.x);
    h23 = cvt2(v.w, v.z);
    float f0 = __uint_as_float(h01 << 16);
    float f1 = __uint_as_float(h01 & 0xFFFF0000u);
    float f2 = __uint_as_float(h23 << 16);
    float f3 = __uint_as_float(h23 & 0xFFFF0000u);
    l01 = cvt2(v.y - f1, v.x - f0);
    l23 = cvt2(v.w - f3, v.z - f2);
}

__device__ __forceinline__ void mma16816(float* d, const uint4& a,
                                         uint32_t b0, uint32_t b1) {
    asm volatile(
        "mma.sync.aligned.m16n8k16.row.col.f32.bf16.bf16.f32 "
        "{%0,%1,%2,%3}, {%4,%5,%6,%7}, {%8,%9}, {%0,%1,%2,%3};"
        : "+f"(d[0]), "+f"(d[1]), "+f"(d[2]), "+f"(d[3])
        : "r"(a.x), "r"(a.y), "r"(a.z), "r"(a.w), "r"(b0), "r"(b1));
}

// ---------------- kernel 1: x -> A-fragment hi/lo arrays ----------------
__global__ __launch_bounds__(256)
void convert_x_kernel(const float* __restrict__ x) {
    int t = blockIdx.x * 256 + threadIdx.x;   // 0..16383
    int mb   = t >> 12;
    int ks   = (t >> 5) & 127;
    int lane = t & 31;
    int g  = lane >> 2;
    int tt = lane & 3;
    int m0 = mb * 16 + g;
    int k0 = ks * 16 + 2 * tt;

    float2 p00 = *reinterpret_cast<const float2*>(&x[m0 * KDIM + k0]);
    float2 p10 = *reinterpret_cast<const float2*>(&x[(m0 + 8) * KDIM + k0]);
    float2 p01 = *reinterpret_cast<const float2*>(&x[m0 * KDIM + k0 + 8]);
    float2 p11 = *reinterpret_cast<const float2*>(&x[(m0 + 8) * KDIM + k0 + 8]);

    uint4 hi, lo;
    float4 v0 = make_float4(p00.x, p00.y, p10.x, p10.y);
    float4 v1 = make_float4(p01.x, p01.y, p11.x, p11.y);
    uint32_t h01, h23, l01, l23;
    split4(v0, h01, h23, l01, l23);
    hi.x = h01; hi.y = h23; lo.x = l01; lo.y = l23;
    split4(v1, h01, h23, l01, l23);
    hi.z = h01; hi.w = h23; lo.z = l01; lo.w = l23;

    g_ahi[t] = hi;
    g_alo[t] = lo;
}

// ---------------- kernel 2: bf16 HMMA GEMM, atomic split-K ----------------
__global__ __launch_bounds__(GT, 1)
void gemm_kernel(const float* __restrict__ Wv, float* __restrict__ out) {
    __shared__ uint32_t SH[128 * PADW];   // W hi, [row][k-pair word], pad 36
    __shared__ uint32_t SL[128 * PADW];   // W lo

    const int tid  = threadIdx.x;
    const int lane = tid & 31;
    const int wid  = tid >> 5;
    const int wrow = wid >> 2;     // m-block 0..3 (m16 each)
    const int wcol = wid & 3;      // n-group 0..3 (n32 each)
    const int g  = lane >> 2;
    const int tt = lane & 3;

    const int n0 = blockIdx.x * NT;
    const int k0 = blockIdx.y * KCH;

    // W loader mapping: warp covers 2 rows x 16 kf4 -> coalesced LDG.128
    const int lrow = tid >> 4;          // 0..31 (+32i)
    const int lkf  = (tid & 15) * 4;    // 0..60

    float acc[4][4];
#pragma unroll
    for (int i = 0; i < 4; i++)
#pragma unroll
        for (int j = 0; j < 4; j++) acc[i][j] = 0.f;

    float4 wr[4];
#pragma unroll
    for (int i = 0; i < 4; i++)
        wr[i] = *reinterpret_cast<const float4*>(
            &Wv[(n0 + lrow + i * 32) * KDIM + k0 + lkf]);

    // A-fragment register double buffer (prefetch depth 1)
    const int ksg0 = blockIdx.y * KSTEPS_CTA;
    const uint4* ahp = &g_ahi[(wrow * 128 + ksg0) * 32 + lane];
    const uint4* alp = &g_alo[(wrow * 128 + ksg0) * 32 + lane];
    uint4 ah_n = ahp[0];
    uint4 al_n = alp[0];

    for (int sc = 0; sc < 4; sc++) {
        __syncthreads();   // prior consumers done
        // convert + store W sub-chunk (rows x k64)
#pragma unroll
        for (int i = 0; i < 4; i++) {
            uint32_t h01, h23, l01, l23;
            split4(wr[i], h01, h23, l01, l23);
            int w = (lrow + i * 32) * PADW + (lkf >> 1);
            *reinterpret_cast<uint2*>(&SH[w]) = make_uint2(h01, h23);
            *reinterpret_cast<uint2*>(&SL[w]) = make_uint2(l01, l23);
        }
        if (sc < 3) {
#pragma unroll
            for (int i = 0; i < 4; i++)
                wr[i] = *reinterpret_cast<const float4*>(
                    &Wv[(n0 + lrow + i * 32) * KDIM + k0 + (sc + 1) * 64 + lkf]);
        }
        __syncthreads();   // tiles ready

#pragma unroll
        for (int ks = 0; ks < 4; ks++) {
            // consume prefetched A, kick off next prefetch (overlaps MMAs)
            uint4 ah = ah_n, al = al_n;
            int nxt = sc * 4 + ks + 1;
            int nxtc = nxt < 16 ? nxt : 15;   // clamped dummy reload on last
            ah_n = ahp[nxtc * 32];
            al_n = alp[nxtc * 32];

            // hoist ALL B fragments for this k-step
            uint32_t bh[4][2], bl[4][2];
#pragma unroll
            for (int nf = 0; nf < 4; nf++) {
                int nrow = wcol * 32 + nf * 8 + g;
                int bw = nrow * PADW + ks * 8 + tt;   // bank = (4g+tt)%32: clean
                bh[nf][0] = SH[bw]; bh[nf][1] = SH[bw + 4];
                bl[nf][0] = SL[bw]; bl[nf][1] = SL[bw + 4];
            }
            // product-major: 4 independent accumulators between same-acc reuse
#pragma unroll
            for (int nf = 0; nf < 4; nf++)
                mma16816(acc[nf], ah, bh[nf][0], bh[nf][1]);
#pragma unroll
            for (int nf = 0; nf < 4; nf++)
                mma16816(acc[nf], ah, bl[nf][0], bl[nf][1]);
#pragma unroll
            for (int nf = 0; nf < 4; nf++)
                mma16816(acc[nf], al, bh[nf][0], bh[nf][1]);
        }
    }

    // epilogue: split-K combine via vector atomics into out
#pragma unroll
    for (int nf = 0; nf < 4; nf++) {
        int m = wrow * 16 + g;
        int n = n0 + wcol * 32 + nf * 8 + 2 * tt;
        atomicAdd(reinterpret_cast<float2*>(&out[m * NDIM + n]),
                  make_float2(acc[nf][0], acc[nf][1]));
        atomicAdd(reinterpret_cast<float2*>(&out[(m + 8) * NDIM + n]),
                  make_float2(acc[nf][2], acc[nf][3]));
    }
}

extern "C" void kernel_launch(void* const* d_in, const int* in_sizes, int n_in,
                              void* d_out, int out_size) {
    // inputs: 0=x [64,1,2048] f32, 1=Wq, 2=bq, 3=Wk, 4=bk, 5=Wv [2048,2048], 6=pos
    const float* x  = (const float*)d_in[0];
    const float* Wv = (const float*)d_in[5];
    float* out = (float*)d_out;

    cudaMemsetAsync(out, 0, (size_t)MDIM * NDIM * sizeof(float));
    convert_x_kernel<<<64, 256>>>(x);
    dim3 grid(NDIM / NT, SPLITK);   // 16 x 8 = 128 CTAs, one wave
    gemm_kernel<<<grid, GT>>>(Wv, out);

    (void)in_sizes; (void)n_in; (void)out_size;
}

// round 5
// speedup vs baseline: 2.6213x; 1.0021x over previous
#include <cuda_runtime.h>
#include <cuda_bf16.h>
#include <cstdint>

// LinearAttentionCell with T=1 reduces algebraically to out = x @ Wv^T
// (memory = outer(k,v); mem_read = (q.k)*v; scale = (q.k) => out = v).
// bf16 HMMA (mma.sync m16n8k16) with 3-product Dekker splitting:
//   fp32 = hi + lo (bf16);  D += Ahi*Bhi + Ahi*Blo + Alo*Bhi  (fp32 accum)
// M=64 (batch) x N=2048 (out channels) x K=2048.
// R5: 256-thread CTAs (NT=64), __launch_bounds__(256,2) -> 2 CTAs/SM,
// 256 CTAs cover all 148 SMs; one CTA's MMA phase overlaps the other's
// load/convert/store phase.

#define KDIM 2048
#define NDIM 2048
#define MDIM 64
#define NT   64           // n per CTA
#define SPLITK 8
#define KCH  256          // k per CTA
#define KSTEPS_CTA 16     // KCH/16
#define GT   256          // gemm threads (8 warps: 4 m-rows x 2 n-cols)

// x pre-split into mma A-fragment order:
// [mb(4)][ks_global(128)][lane(32)] -> uint4 (a0..a3)
__device__ __align__(16) uint4 g_ahi[4 * 128 * 32];
__device__ __align__(16) uint4 g_alo[4 * 128 * 32];

// padded smem W tile: 64 rows x 32 k-pair words, row stride 36 words
#define PADW 36

__device__ __forceinline__ uint32_t cvt2(float hi_e, float lo_e) {
    // packs: low 16 = bf16(lo_e), high 16 = bf16(hi_e)
    uint32_t r;
    asm("cvt.rn.bf16x2.f32 %0, %1, %2;" : "=r"(r) : "f"(hi_e), "f"(lo_e));
    return r;
}

__device__ __forceinline__ void split4(float4 v, uint32_t& h01, uint32_t& h23,
                                       uint32_t& l01, uint32_t& l23) {
    h01 = cvt2(v.y, v.x);
    h23 = cvt2(v.w, v.z);
    float f0 = __uint_as_float(h01 << 16);
    float f1 = __uint_as_float(h01 & 0xFFFF0000u);
    float f2 = __uint_as_float(h23 << 16);
    float f3 = __uint_as_float(h23 & 0xFFFF0000u);
    l01 = cvt2(v.y - f1, v.x - f0);
    l23 = cvt2(v.w - f3, v.z - f2);
}

__device__ __forceinline__ void mma16816(float* d, const uint4& a,
                                         uint32_t b0, uint32_t b1) {
    asm volatile(
        "mma.sync.aligned.m16n8k16.row.col.f32.bf16.bf16.f32 "
        "{%0,%1,%2,%3}, {%4,%5,%6,%7}, {%8,%9}, {%0,%1,%2,%3};"
        : "+f"(d[0]), "+f"(d[1]), "+f"(d[2]), "+f"(d[3])
        : "r"(a.x), "r"(a.y), "r"(a.z), "r"(a.w), "r"(b0), "r"(b1));
}

// ---------------- kernel 1: x -> A-fragment hi/lo arrays ----------------
__global__ __launch_bounds__(256)
void convert_x_kernel(const float* __restrict__ x) {
    int t = blockIdx.x * 256 + threadIdx.x;   // 0..16383
    int mb   = t >> 12;
    int ks   = (t >> 5) & 127;
    int lane = t & 31;
    int g  = lane >> 2;
    int tt = lane & 3;
    int m0 = mb * 16 + g;
    int k0 = ks * 16 + 2 * tt;

    float2 p00 = *reinterpret_cast<const float2*>(&x[m0 * KDIM + k0]);
    float2 p10 = *reinterpret_cast<const float2*>(&x[(m0 + 8) * KDIM + k0]);
    float2 p01 = *reinterpret_cast<const float2*>(&x[m0 * KDIM + k0 + 8]);
    float2 p11 = *reinterpret_cast<const float2*>(&x[(m0 + 8) * KDIM + k0 + 8]);

    uint4 hi, lo;
    float4 v0 = make_float4(p00.x, p00.y, p10.x, p10.y);
    float4 v1 = make_float4(p01.x, p01.y, p11.x, p11.y);
    uint32_t h01, h23, l01, l23;
    split4(v0, h01, h23, l01, l23);
    hi.x = h01; hi.y = h23; lo.x = l01; lo.y = l23;
    split4(v1, h01, h23, l01, l23);
    hi.z = h01; hi.w = h23; lo.z = l01; lo.w = l23;

    g_ahi[t] = hi;
    g_alo[t] = lo;
}

// ---------------- kernel 2: bf16 HMMA GEMM, atomic split-K ----------------
__global__ __launch_bounds__(GT, 2)
void gemm_kernel(const float* __restrict__ Wv, float* __restrict__ out) {
    __shared__ uint32_t SH[NT * PADW];   // W hi, [row][k-pair word], pad 36
    __shared__ uint32_t SL[NT * PADW];   // W lo

    const int tid  = threadIdx.x;
    const int lane = tid & 31;
    const int wid  = tid >> 5;
    const int wrow = wid >> 1;     // m-block 0..3 (m16 each)
    const int wcol = wid & 1;      // n-group 0..1 (n32 each)
    const int g  = lane >> 2;
    const int tt = lane & 3;

    const int n0 = blockIdx.x * NT;
    const int k0 = blockIdx.y * KCH;

    // W loader mapping: 64 rows x 16 float4 per chunk = 4 per thread
    const int lrow = tid >> 4;          // 0..15 (+16i)
    const int lkf  = (tid & 15) * 4;    // 0..60

    float acc[4][4];
#pragma unroll
    for (int i = 0; i < 4; i++)
#pragma unroll
        for (int j = 0; j < 4; j++) acc[i][j] = 0.f;

    float4 wr[4];
#pragma unroll
    for (int i = 0; i < 4; i++)
        wr[i] = *reinterpret_cast<const float4*>(
            &Wv[(n0 + lrow + i * 16) * KDIM + k0 + lkf]);

    // A-fragment register double buffer (prefetch depth 1)
    const int ksg0 = blockIdx.y * KSTEPS_CTA;
    const uint4* ahp = &g_ahi[(wrow * 128 + ksg0) * 32 + lane];
    const uint4* alp = &g_alo[(wrow * 128 + ksg0) * 32 + lane];
    uint4 ah_n = ahp[0];
    uint4 al_n = alp[0];

    for (int sc = 0; sc < 4; sc++) {
        __syncthreads();   // prior consumers done
        // convert + store W sub-chunk (64 rows x k64)
#pragma unroll
        for (int i = 0; i < 4; i++) {
            uint32_t h01, h23, l01, l23;
            split4(wr[i], h01, h23, l01, l23);
            int w = (lrow + i * 16) * PADW + (lkf >> 1);
            *reinterpret_cast<uint2*>(&SH[w]) = make_uint2(h01, h23);
            *reinterpret_cast<uint2*>(&SL[w]) = make_uint2(l01, l23);
        }
        if (sc < 3) {
#pragma unroll
            for (int i = 0; i < 4; i++)
                wr[i] = *reinterpret_cast<const float4*>(
                    &Wv[(n0 + lrow + i * 16) * KDIM + k0 + (sc + 1) * 64 + lkf]);
        }
        __syncthreads();   // tiles ready

#pragma unroll
        for (int ks = 0; ks < 4; ks++) {
            // consume prefetched A, kick off next prefetch (overlaps MMAs)
            uint4 ah = ah_n, al = al_n;
            int nxt = sc * 4 + ks + 1;
            int nxtc = nxt < 16 ? nxt : 15;   // clamped dummy reload on last
            ah_n = ahp[nxtc * 32];
            al_n = alp[nxtc * 32];

            // hoist ALL B fragments for this k-step
            uint32_t bh[4][2], bl[4][2];
#pragma unroll
            for (int nf = 0; nf < 4; nf++) {
                int nrow = wcol * 32 + nf * 8 + g;
                int bw = nrow * PADW + ks * 8 + tt;   // bank = (4g+tt)%32: clean
                bh[nf][0] = SH[bw]; bh[nf][1] = SH[bw + 4];
                bl[nf][0] = SL[bw]; bl[nf][1] = SL[bw + 4];
            }
            // product-major: 4 independent accumulators between same-acc reuse
#pragma unroll
            for (int nf = 0; nf < 4; nf++)
                mma16816(acc[nf], ah, bh[nf][0], bh[nf][1]);
#pragma unroll
            for (int nf = 0; nf < 4; nf++)
                mma16816(acc[nf], ah, bl[nf][0], bl[nf][1]);
#pragma unroll
            for (int nf = 0; nf < 4; nf++)
                mma16816(acc[nf], al, bh[nf][0], bh[nf][1]);
        }
    }

    // epilogue: split-K combine via vector atomics into out
#pragma unroll
    for (int nf = 0; nf < 4; nf++) {
        int m = wrow * 16 + g;
        int n = n0 + wcol * 32 + nf * 8 + 2 * tt;
        atomicAdd(reinterpret_cast<float2*>(&out[m * NDIM + n]),
                  make_float2(acc[nf][0], acc[nf][1]));
        atomicAdd(reinterpret_cast<float2*>(&out[(m + 8) * NDIM + n]),
                  make_float2(acc[nf][2], acc[nf][3]));
    }
}

extern "C" void kernel_launch(void* const* d_in, const int* in_sizes, int n_in,
                              void* d_out, int out_size) {
    // inputs: 0=x [64,1,2048] f32, 1=Wq, 2=bq, 3=Wk, 4=bk, 5=Wv [2048,2048], 6=pos
    const float* x  = (const float*)d_in[0];
    const float* Wv = (const float*)d_in[5];
    float* out = (float*)d_out;

    cudaMemsetAsync(out, 0, (size_t)MDIM * NDIM * sizeof(float));
    convert_x_kernel<<<64, 256>>>(x);
    dim3 grid(NDIM / NT, SPLITK);   // 32 x 8 = 256 CTAs, 2 per SM
    gemm_kernel<<<grid, GT>>>(Wv, out);

    (void)in_sizes; (void)n_in; (void)out_size;
}

// round 6
// speedup vs baseline: 2.6552x; 1.0129x over previous
#include <cuda_runtime.h>
#include <cuda_bf16.h>
#include <cstdint>

// LinearAttentionCell with T=1 reduces algebraically to out = x @ Wv^T
// (memory = outer(k,v); mem_read = (q.k)*v; scale = (q.k) => out = v).
// bf16 HMMA (mma.sync m16n8k16) with 3-product Dekker splitting:
//   fp32 = hi + lo (bf16);  D += Ahi*Bhi + Ahi*Blo + Alo*Bhi  (fp32 accum)
// M=64 (batch) x N=2048 (out channels) x K=2048.
// R6: NO shared memory, NO barriers in the GEMM. W is read straight from
// global in B-fragment order (LDG.64 pairs, 100% sector efficiency) and
// Dekker-split in registers; A comes pre-split in fragment order. Pure
// scoreboard-pipelined LDG+MMA stream with depth-1 register prefetch.

#define KDIM 2048
#define NDIM 2048
#define MDIM 64
#define NT   64           // n per CTA
#define SPLITK 8
#define KCH  256          // k per CTA
#define KSTEPS_CTA 16     // KCH/16
#define GT   256          // 8 warps: 2 m32-rows x 4 n16-cols

// x pre-split into mma A-fragment order:
// [mb(4)][ks_global(128)][lane(32)] -> uint4 (a0..a3)
__device__ __align__(16) uint4 g_ahi[4 * 128 * 32];
__device__ __align__(16) uint4 g_alo[4 * 128 * 32];

__device__ __forceinline__ uint32_t cvt2(float hi_e, float lo_e) {
    // packs: low 16 = bf16(lo_e), high 16 = bf16(hi_e)
    uint32_t r;
    asm("cvt.rn.bf16x2.f32 %0, %1, %2;" : "=r"(r) : "f"(hi_e), "f"(lo_e));
    return r;
}

// split a float2 (two consecutive k values) into one bf16x2 hi word + lo word
__device__ __forceinline__ void split2(float2 v, uint32_t& h, uint32_t& l) {
    h = cvt2(v.y, v.x);
    float f0 = __uint_as_float(h << 16);
    float f1 = __uint_as_float(h & 0xFFFF0000u);
    l = cvt2(v.y - f1, v.x - f0);
}

__device__ __forceinline__ void split4(float4 v, uint32_t& h01, uint32_t& h23,
                                       uint32_t& l01, uint32_t& l23) {
    split2(make_float2(v.x, v.y), h01, l01);
    split2(make_float2(v.z, v.w), h23, l23);
}

__device__ __forceinline__ void mma16816(float* d, const uint4& a,
                                         uint32_t b0, uint32_t b1) {
    asm volatile(
        "mma.sync.aligned.m16n8k16.row.col.f32.bf16.bf16.f32 "
        "{%0,%1,%2,%3}, {%4,%5,%6,%7}, {%8,%9}, {%0,%1,%2,%3};"
        : "+f"(d[0]), "+f"(d[1]), "+f"(d[2]), "+f"(d[3])
        : "r"(a.x), "r"(a.y), "r"(a.z), "r"(a.w), "r"(b0), "r"(b1));
}

// ---------------- kernel 1: x -> A-fragment hi/lo arrays ----------------
__global__ __launch_bounds__(256)
void convert_x_kernel(const float* __restrict__ x) {
    int t = blockIdx.x * 256 + threadIdx.x;   // 0..16383
    int mb   = t >> 12;
    int ks   = (t >> 5) & 127;
    int lane = t & 31;
    int g  = lane >> 2;
    int tt = lane & 3;
    int m0 = mb * 16 + g;
    int k0 = ks * 16 + 2 * tt;

    float2 p00 = *reinterpret_cast<const float2*>(&x[m0 * KDIM + k0]);
    float2 p10 = *reinterpret_cast<const float2*>(&x[(m0 + 8) * KDIM + k0]);
    float2 p01 = *reinterpret_cast<const float2*>(&x[m0 * KDIM + k0 + 8]);
    float2 p11 = *reinterpret_cast<const float2*>(&x[(m0 + 8) * KDIM + k0 + 8]);

    uint4 hi, lo;
    float4 v0 = make_float4(p00.x, p00.y, p10.x, p10.y);
    float4 v1 = make_float4(p01.x, p01.y, p11.x, p11.y);
    uint32_t h01, h23, l01, l23;
    split4(v0, h01, h23, l01, l23);
    hi.x = h01; hi.y = h23; lo.x = l01; lo.y = l23;
    split4(v1, h01, h23, l01, l23);
    hi.z = h01; hi.w = h23; lo.z = l01; lo.w = l23;

    g_ahi[t] = hi;
    g_alo[t] = lo;
}

// ---------------- kernel 2: smem-free HMMA GEMM, atomic split-K ----------------
__global__ __launch_bounds__(GT, 2)
void gemm_kernel(const float* __restrict__ Wv, float* __restrict__ out) {
    const int tid  = threadIdx.x;
    const int lane = tid & 31;
    const int wid  = tid >> 5;
    const int wcol = wid & 3;      // n16 group 0..3
    const int wrow = wid >> 2;     // m32 group 0..1
    const int g  = lane >> 2;
    const int tt = lane & 3;

    const int n0   = blockIdx.x * NT;
    const int ksg0 = blockIdx.y * KSTEPS_CTA;
    const int k0   = blockIdx.y * KCH;

    // A fragment pointers (pre-split, fragment order; stride 32 uint4 per k-step)
    const uint4* ah0p = &g_ahi[((wrow * 2 + 0) * 128 + ksg0) * 32 + lane];
    const uint4* al0p = &g_alo[((wrow * 2 + 0) * 128 + ksg0) * 32 + lane];
    const uint4* ah1p = &g_ahi[((wrow * 2 + 1) * 128 + ksg0) * 32 + lane];
    const uint4* al1p = &g_alo[((wrow * 2 + 1) * 128 + ksg0) * 32 + lane];

    // W fragment pointers: lane reads W[n0+wcol*16+nf*8+g][k0+ks*16+tt*2 (+8)]
    const float* w0p = Wv + (size_t)(n0 + wcol * 16 + 0 * 8 + g) * KDIM + k0 + tt * 2;
    const float* w1p = Wv + (size_t)(n0 + wcol * 16 + 1 * 8 + g) * KDIM + k0 + tt * 2;

    float acc[2][2][4];
#pragma unroll
    for (int a = 0; a < 2; a++)
#pragma unroll
        for (int b = 0; b < 2; b++)
#pragma unroll
            for (int c = 0; c < 4; c++) acc[a][b][c] = 0.f;

    // depth-1 register prefetch
    uint4 ah0n = ah0p[0], al0n = al0p[0], ah1n = ah1p[0], al1n = al1p[0];
    float2 wa0n = *reinterpret_cast<const float2*>(w0p);
    float2 wa1n = *reinterpret_cast<const float2*>(w0p + 8);
    float2 wb0n = *reinterpret_cast<const float2*>(w1p);
    float2 wb1n = *reinterpret_cast<const float2*>(w1p + 8);

#pragma unroll
    for (int ks = 0; ks < KSTEPS_CTA; ks++) {
        uint4 ah0 = ah0n, al0 = al0n, ah1 = ah1n, al1 = al1n;
        float2 wa0 = wa0n, wa1 = wa1n, wb0 = wb0n, wb1 = wb1n;

        int nx = (ks + 1 < KSTEPS_CTA) ? ks + 1 : ks;   // clamped dummy on last
        ah0n = ah0p[nx * 32]; al0n = al0p[nx * 32];
        ah1n = ah1p[nx * 32]; al1n = al1p[nx * 32];
        wa0n = *reinterpret_cast<const float2*>(w0p + nx * 16);
        wa1n = *reinterpret_cast<const float2*>(w0p + nx * 16 + 8);
        wb0n = *reinterpret_cast<const float2*>(w1p + nx * 16);
        wb1n = *reinterpret_cast<const float2*>(w1p + nx * 16 + 8);

        // Dekker-split W in registers
        uint32_t bh00, bh01, bh10, bh11, bl00, bl01, bl10, bl11;
        split2(wa0, bh00, bl00);
        split2(wa1, bh01, bl01);
        split2(wb0, bh10, bl10);
        split2(wb1, bh11, bl11);

        // product-major: 4 independent accumulators between same-acc reuse
        mma16816(acc[0][0], ah0, bh00, bh01);
        mma16816(acc[0][1], ah0, bh10, bh11);
        mma16816(acc[1][0], ah1, bh00, bh01);
        mma16816(acc[1][1], ah1, bh10, bh11);

        mma16816(acc[0][0], ah0, bl00, bl01);
        mma16816(acc[0][1], ah0, bl10, bl11);
        mma16816(acc[1][0], ah1, bl00, bl01);
        mma16816(acc[1][1], ah1, bl10, bl11);

        mma16816(acc[0][0], al0, bh00, bh01);
        mma16816(acc[0][1], al0, bh10, bh11);
        mma16816(acc[1][0], al1, bh00, bh01);
        mma16816(acc[1][1], al1, bh10, bh11);
    }

    // epilogue: split-K combine via vector atomics into out
#pragma unroll
    for (int mb = 0; mb < 2; mb++) {
#pragma unroll
        for (int nf = 0; nf < 2; nf++) {
            int m = (wrow * 2 + mb) * 16 + g;
            int n = n0 + wcol * 16 + nf * 8 + 2 * tt;
            atomicAdd(reinterpret_cast<float2*>(&out[m * NDIM + n]),
                      make_float2(acc[mb][nf][0], acc[mb][nf][1]));
            atomicAdd(reinterpret_cast<float2*>(&out[(m + 8) * NDIM + n]),
                      make_float2(acc[mb][nf][2], acc[mb][nf][3]));
        }
    }
}

extern "C" void kernel_launch(void* const* d_in, const int* in_sizes, int n_in,
                              void* d_out, int out_size) {
    // inputs: 0=x [64,1,2048] f32, 1=Wq, 2=bq, 3=Wk, 4=bk, 5=Wv [2048,2048], 6=pos
    const float* x  = (const float*)d_in[0];
    const float* Wv = (const float*)d_in[5];
    float* out = (float*)d_out;

    cudaMemsetAsync(out, 0, (size_t)MDIM * NDIM * sizeof(float));
    convert_x_kernel<<<64, 256>>>(x);
    dim3 grid(NDIM / NT, SPLITK);   // 32 x 8 = 256 CTAs
    gemm_kernel<<<grid, GT>>>(Wv, out);

    (void)in_sizes; (void)n_in; (void)out_size;
}